// round 14
// baseline (speedup 1.0000x reference)
#include <cuda_runtime.h>
#include <cuda_bf16.h>
#include <cuda_fp16.h>
#include <math.h>
#include <stdint.h>

#define NB       8192      // batch B
#define E_DIM    1024
#define P_DIM    512
#define D_DIM    1024      // 2P
#define M2       16384     // 2B rows in projection GEMM

// Scratch (no allocations allowed)
__device__ __half g_zb[(size_t)NB * D_DIM];             // 16 MB f16 proj output z
__device__ uint8_t g_zn8[(size_t)NB * D_DIM];           // 8 MB e4m3 normalized (x16)
__device__ __half g_xh[(size_t)NB * 2 * E_DIM];         // 32 MB f16 relu(x)
__device__ __half g_wh[(size_t)E_DIM * P_DIM];          // 1 MB f16 w
__device__ float g_rowsum[NB];
__device__ float g_pos[NB];

#define ZN_SCALE      16.0f
#define LOGIT_SCALE   (10.0f / 256.0f)      // 10 / ZN_SCALE^2

// ---------------------------------------------------------------------------
// PTX helpers (sm_80/89-era only, no arch-accelerated features)
// ---------------------------------------------------------------------------
__device__ __forceinline__ uint32_t smem_u32(const void* p) {
    uint32_t a;
    asm("{ .reg .u64 t; cvta.to.shared.u64 t, %1; cvt.u32.u64 %0, t; }" : "=r"(a) : "l"(p));
    return a;
}
__device__ __forceinline__ void cp_async16(uint32_t dst, const void* src) {
    asm volatile("cp.async.cg.shared.global [%0], [%1], 16;" :: "r"(dst), "l"(src));
}
#define CP_COMMIT() asm volatile("cp.async.commit_group;" ::: "memory")
#define CP_WAIT(N)  asm volatile("cp.async.wait_group %0;" :: "n"(N) : "memory")

__device__ __forceinline__ void ldsm_x4(uint32_t& r0, uint32_t& r1, uint32_t& r2,
                                        uint32_t& r3, uint32_t addr) {
    asm volatile("ldmatrix.sync.aligned.m8n8.x4.shared.b16 {%0,%1,%2,%3}, [%4];"
                 : "=r"(r0), "=r"(r1), "=r"(r2), "=r"(r3) : "r"(addr));
}
__device__ __forceinline__ void ldsm_x4_t(uint32_t& r0, uint32_t& r1, uint32_t& r2,
                                          uint32_t& r3, uint32_t addr) {
    asm volatile("ldmatrix.sync.aligned.m8n8.x4.trans.shared.b16 {%0,%1,%2,%3}, [%4];"
                 : "=r"(r0), "=r"(r1), "=r"(r2), "=r"(r3) : "r"(addr));
}
// f16 inputs, f16 accumulators (2 regs) - used by proj
__device__ __forceinline__ void mma_f16(uint32_t* c, const uint32_t* a, const uint32_t* b) {
    asm volatile(
        "mma.sync.aligned.m16n8k16.row.col.f16.f16.f16.f16 "
        "{%0,%1}, {%2,%3,%4,%5}, {%6,%7}, {%0,%1};"
        : "+r"(c[0]), "+r"(c[1])
        : "r"(a[0]), "r"(a[1]), "r"(a[2]), "r"(a[3]), "r"(b[0]), "r"(b[1]));
}
// e4m3 inputs, f16 accumulators, K=32 - used by sim
__device__ __forceinline__ void mma_fp8(uint32_t* c, const uint32_t* a, const uint32_t* b) {
    asm volatile(
        "mma.sync.aligned.m16n8k32.row.col.f16.e4m3.e4m3.f16 "
        "{%0,%1}, {%2,%3,%4,%5}, {%6,%7}, {%0,%1};"
        : "+r"(c[0]), "+r"(c[1])
        : "r"(a[0]), "r"(a[1]), "r"(a[2]), "r"(a[3]), "r"(b[0]), "r"(b[1]));
}
// pack two floats into e4m3x2 (byte0 = lo, byte1 = hi)
__device__ __forceinline__ uint16_t cvt_e4m3x2(float hi, float lo) {
    uint16_t r;
    asm("cvt.rn.satfinite.e4m3x2.f32 %0, %1, %2;" : "=h"(r) : "f"(hi), "f"(lo));
    return r;
}

// ---------------------------------------------------------------------------
// Kernel 0: convert relu(x)->f16 (g_xh) and w->f16 (g_wh)
// ---------------------------------------------------------------------------
#define XCVT_BLOCKS 16384
#define WCVT_BLOCKS 512
__global__ __launch_bounds__(256) void convert_kernel(const float* __restrict__ x,
                                                      const float* __restrict__ w) {
    const int tid = threadIdx.x;
    if (blockIdx.x < XCVT_BLOCKS) {
        const size_t i = ((size_t)blockIdx.x * 256 + tid);
        float4 v = *(const float4*)(x + i * 4);
        __half2 p0 = __floats2half2_rn(fmaxf(v.x, 0.f), fmaxf(v.y, 0.f));
        __half2 p1 = __floats2half2_rn(fmaxf(v.z, 0.f), fmaxf(v.w, 0.f));
        uint2 o; o.x = *(uint32_t*)&p0; o.y = *(uint32_t*)&p1;
        *(uint2*)(g_xh + i * 4) = o;
    } else {
        const size_t i = ((size_t)(blockIdx.x - XCVT_BLOCKS) * 256 + tid);
        float4 v = *(const float4*)(w + i * 4);
        __half2 p0 = __floats2half2_rn(v.x, v.y);
        __half2 p1 = __floats2half2_rn(v.z, v.w);
        uint2 o; o.x = *(uint32_t*)&p0; o.y = *(uint32_t*)&p1;
        *(uint2*)(g_wh + i * 4) = o;
    }
}

// ---------------------------------------------------------------------------
// Kernel 1: f16-acc HMMA projection (R13, unchanged), 4 CTAs/SM single wave.
// ---------------------------------------------------------------------------
#define AROW_BYTES  80
#define PA_BYTES    (128 * AROW_BYTES)       // 10240
#define BROW_BYTES  272                      // 128 f16 + 16B pad
#define PB_BYTES    (32 * BROW_BYTES)        // 8704
#define PSTAGE      (PA_BYTES + PB_BYTES)    // 18944
#define PSTAGES     3
#define PROJ_SMEM   (PSTAGES * PSTAGE)       // 56832
#define PCHUNKS     (E_DIM / 32)             // 32

extern __shared__ char dsmem[];

__device__ __forceinline__ void proj_prefetch(uint32_t stA, uint32_t stB,
                                              int m0, int n0, int kb, int tid) {
#pragma unroll
    for (int it = 0; it < 4; it++) {        // A: 128 rows x 4 segs
        const int j = tid + it * 128;
        const int row = j >> 2, seg = j & 3;
        const int r = m0 + row;
        const __half* src = g_xh + (size_t)(r & (NB - 1)) * 2048
                          + (size_t)(r >> 13) * 1024 + kb + (seg << 3);
        cp_async16(stA + row * AROW_BYTES + seg * 16, src);
    }
#pragma unroll
    for (int it = 0; it < 4; it++) {        // B: 32 k-rows x 16 segs
        const int j = tid + it * 128;
        const int row = j >> 4, seg = j & 15;
        const __half* src = g_wh + (size_t)(kb + row) * P_DIM + n0 + (seg << 3);
        cp_async16(stB + row * BROW_BYTES + seg * 16, src);
    }
}

__global__ __launch_bounds__(128, 4)
void proj_kernel(const float* __restrict__ bias) {
    const int tid = threadIdx.x;
    const int wid = tid >> 5;
    const int lane = tid & 31;
    const int warp_m = wid >> 1;
    const int warp_n = wid & 1;
    const int m0 = blockIdx.y * 128;
    const int n0 = blockIdx.x * 128;

    const uint32_t sbase = smem_u32(dsmem);
    uint32_t stA[PSTAGES], stB[PSTAGES];
#pragma unroll
    for (int s = 0; s < PSTAGES; s++) {
        stA[s] = sbase + s * PSTAGE;
        stB[s] = stA[s] + PA_BYTES;
    }

    const uint32_t aOff = (warp_m * 64 + (lane & 15)) * AROW_BYTES + (lane >> 4) * 16;
    const uint32_t bRow = (lane & 7) + ((lane >> 3) & 1) * 8;
    const uint32_t bCol = warp_n * 64 + (lane >> 4) * 8;

    uint32_t acc[4][8][2];
#pragma unroll
    for (int mi = 0; mi < 4; mi++)
#pragma unroll
        for (int ni = 0; ni < 8; ni++) { acc[mi][ni][0] = 0u; acc[mi][ni][1] = 0u; }

    proj_prefetch(stA[0], stB[0], m0, n0, 0, tid);  CP_COMMIT();
    proj_prefetch(stA[1], stB[1], m0, n0, 32, tid); CP_COMMIT();

    for (int kc = 0; kc < PCHUNKS; kc++) {
        CP_WAIT(1);
        __syncthreads();
        const int s = kc % PSTAGES;

#pragma unroll
        for (int ks = 0; ks < 2; ks++) {
            uint32_t aF[4][4], bF[4][4];
#pragma unroll
            for (int mi = 0; mi < 4; mi++)
                ldsm_x4(aF[mi][0], aF[mi][1], aF[mi][2], aF[mi][3],
                        stA[s] + aOff + mi * 16 * AROW_BYTES + ks * 32);
#pragma unroll
            for (int p = 0; p < 4; p++)
                ldsm_x4_t(bF[p][0], bF[p][1], bF[p][2], bF[p][3],
                          stB[s] + (ks * 16 + bRow) * BROW_BYTES + (bCol + p * 16) * 2);

            if (ks == 0) {
                if (kc + 2 < PCHUNKS) {
                    const int sn = (kc + 2) % PSTAGES;
                    proj_prefetch(stA[sn], stB[sn], m0, n0, (kc + 2) * 32, tid);
                }
                CP_COMMIT();
            }

#pragma unroll
            for (int mi = 0; mi < 4; mi++)
#pragma unroll
                for (int ni = 0; ni < 8; ni++)
                    mma_f16(acc[mi][ni], aF[mi], &bF[ni >> 1][(ni & 1) * 2]);
        }
    }

    const int groupID = lane >> 2, tIdx = lane & 3;
    const int cb = n0 + warp_n * 64 + tIdx * 2;
#pragma unroll
    for (int mi = 0; mi < 4; mi++)
#pragma unroll
        for (int hh = 0; hh < 2; hh++) {
            const int r = m0 + warp_m * 64 + mi * 16 + hh * 8 + groupID;
            const int ib = r & (NB - 1);
            const int half_sel = r >> 13;
            __half* outRow = g_zb + (size_t)ib * D_DIM + half_sel * P_DIM;
#pragma unroll
            for (int ni = 0; ni < 8; ni++) {
                const int c = cb + ni * 8;
                __half2 hv = *(__half2*)&acc[mi][ni][hh];
                __half2 v = __floats2half2_rn(
                    __half2float(hv.x) + __ldg(bias + c),
                    __half2float(hv.y) + __ldg(bias + c + 1));
                *(uint32_t*)(outRow + c) = *(uint32_t*)&v;
            }
        }
}

// ---------------------------------------------------------------------------
// Kernel 2: per-row L2 normalize (f16 in) -> e4m3 x16 (g_zn8), zero g_rowsum
// ---------------------------------------------------------------------------
__global__ __launch_bounds__(256) void norm_kernel() {
    __shared__ float red[256];
    const __half* row = g_zb + (size_t)blockIdx.x * D_DIM;
    uint2 u = *(const uint2*)(row + threadIdx.x * 4);
    __half2 b0 = *(__half2*)&u.x;
    __half2 b1 = *(__half2*)&u.y;
    float v0 = __half2float(b0.x), v1 = __half2float(b0.y);
    float v2 = __half2float(b1.x), v3 = __half2float(b1.y);
    red[threadIdx.x] = v0 * v0 + v1 * v1 + v2 * v2 + v3 * v3;
    __syncthreads();
    for (int off = 128; off > 0; off >>= 1) {
        if (threadIdx.x < off) red[threadIdx.x] += red[threadIdx.x + off];
        __syncthreads();
    }
    const float inv = ZN_SCALE / fmaxf(sqrtf(red[0]), 1e-8f);
    uint16_t p01 = cvt_e4m3x2(v1 * inv, v0 * inv);   // byte0=v0, byte1=v1
    uint16_t p23 = cvt_e4m3x2(v3 * inv, v2 * inv);
    uint32_t packed = (uint32_t)p01 | ((uint32_t)p23 << 16);
    *(uint32_t*)(g_zn8 + ((size_t)blockIdx.x << 10) + threadIdx.x * 4) = packed;
    if (threadIdx.x == 0) g_rowsum[blockIdx.x] = 0.f;
}

// ---------------------------------------------------------------------------
// Kernel 3: FP8 HMMA sim GEMM (upper triangle), block 128x128, 4 warps
// (64x64), BK=64 fp8 (2 x k32 steps), 3 stages, WAIT(1), 3 CTAs/SM.
// Fragment addressing identical to f16 path via fp8-as-b16 reinterpretation.
// ---------------------------------------------------------------------------
#define ROW_BYTES   80                        // 64 fp8 + 16B pad
#define TILE_BYTES  (128 * ROW_BYTES)         // 10240
#define STAGE_BYTES (2 * TILE_BYTES)          // 20480
#define SSTAGES     3
#define SIM_SMEM    (SSTAGES * STAGE_BYTES)   // 61440
#define SCHUNKS     (D_DIM / 64)              // 16
#define TRI_BLOCKS  2080

__device__ __forceinline__ void sim_prefetch(uint32_t stageA, uint32_t stageB,
                                             int r0, int c0, int kb, int tid) {
#pragma unroll
    for (int it = 0; it < 4; it++) {
        const int i = tid + it * 128;
        const int row = i >> 2, seg = i & 3;
        const uint32_t d = row * ROW_BYTES + seg * 16;
        cp_async16(stageA + d, g_zn8 + (((size_t)(r0 + row)) << 10) + kb + (seg << 4));
        cp_async16(stageB + d, g_zn8 + (((size_t)(c0 + row)) << 10) + kb + (seg << 4));
    }
}

__global__ __launch_bounds__(128, 3)
void sim_kernel() {
    // map t -> (by, bx) upper triangle, bx >= by
    const int t = blockIdx.x;
    int by = (int)((129.0f - sqrtf(129.0f * 129.0f - 8.0f * (float)t)) * 0.5f);
    if (by > 63) by = 63;
    if (by < 0) by = 0;
    while (by * 64 - (by * (by - 1)) / 2 > t) by--;
    while ((by + 1) * 64 - ((by + 1) * by) / 2 <= t) by++;
    const int bx = by + (t - (by * 64 - (by * (by - 1)) / 2));

    const int tid = threadIdx.x;
    const int wid = tid >> 5;
    const int lane = tid & 31;
    const int warp_m = wid >> 1;             // 0..1
    const int warp_n = wid & 1;              // 0..1
    const int r0 = by * 128;
    const int c0 = bx * 128;

    const uint32_t sbase = smem_u32(dsmem);
    uint32_t stA[SSTAGES], stB[SSTAGES];
#pragma unroll
    for (int s = 0; s < SSTAGES; s++) {
        stA[s] = sbase + s * STAGE_BYTES;
        stB[s] = stA[s] + TILE_BYTES;
    }

    const uint32_t aOff = (warp_m * 64 + (lane & 15)) * ROW_BYTES + (lane >> 4) * 16;
    const uint32_t bOff = (warp_n * 64 + ((lane >> 4) & 1) * 8 + (lane & 7)) * ROW_BYTES
                        + ((lane >> 3) & 1) * 16;

    uint32_t acc[4][8][2];                   // f16x2 accumulators
#pragma unroll
    for (int mi = 0; mi < 4; mi++)
#pragma unroll
        for (int ni = 0; ni < 8; ni++) { acc[mi][ni][0] = 0u; acc[mi][ni][1] = 0u; }

    sim_prefetch(stA[0], stB[0], r0, c0, 0, tid);  CP_COMMIT();
    sim_prefetch(stA[1], stB[1], r0, c0, 64, tid); CP_COMMIT();

    for (int kc = 0; kc < SCHUNKS; kc++) {
        CP_WAIT(1);
        __syncthreads();
        const int s = kc % SSTAGES;

        uint32_t aF[2][4][4], bF[2][4][4];
#pragma unroll
        for (int ks = 0; ks < 2; ks++) {     // ks = k32 step (32 bytes)
#pragma unroll
            for (int mi = 0; mi < 4; mi++)
                ldsm_x4(aF[ks][mi][0], aF[ks][mi][1], aF[ks][mi][2], aF[ks][mi][3],
                        stA[s] + aOff + mi * 16 * ROW_BYTES + ks * 32);
#pragma unroll
            for (int p = 0; p < 4; p++)
                ldsm_x4(bF[ks][p][0], bF[ks][p][1], bF[ks][p][2], bF[ks][p][3],
                        stB[s] + bOff + p * 16 * ROW_BYTES + ks * 32);
        }

        if (kc + 2 < SCHUNKS) {
            const int sn = (kc + 2) % SSTAGES;
            sim_prefetch(stA[sn], stB[sn], r0, c0, (kc + 2) * 64, tid);
        }
        CP_COMMIT();

#pragma unroll
        for (int ks = 0; ks < 2; ks++)
#pragma unroll
            for (int mi = 0; mi < 4; mi++)
#pragma unroll
                for (int ni = 0; ni < 8; ni++)
                    mma_fp8(acc[mi][ni], aF[ks][mi], &bF[ks][ni >> 1][(ni & 1) * 2]);
    }

    // ---------------- fused epilogue ----------------
    const bool isDiag = (bx == by);
    const bool hasPos = (bx == (by ^ 32));
    const int groupID = lane >> 2, tIdx = lane & 3;
    const int rbase = r0 + warp_m * 64 + groupID;
    const int cbase = c0 + warp_n * 64 + tIdx * 2;

    float rs[4][2];                          // [mi][rowhalf]
    float cs[8][2];                          // [ni][colpair]
#pragma unroll
    for (int i = 0; i < 4; i++) { rs[i][0] = rs[i][1] = 0.f; }
#pragma unroll
    for (int i = 0; i < 8; i++) { cs[i][0] = cs[i][1] = 0.f; }

#pragma unroll
    for (int mi = 0; mi < 4; mi++)
#pragma unroll
        for (int ni = 0; ni < 8; ni++)
#pragma unroll
            for (int hh = 0; hh < 2; hh++) {
                const int r = rbase + mi * 16 + hh * 8;
                __half2 hv = *(__half2*)&acc[mi][ni][hh];
                float v[2] = {__half2float(hv.x), __half2float(hv.y)};
#pragma unroll
                for (int cc = 0; cc < 2; cc++) {
                    const int c = cbase + ni * 8 + cc;
                    const float logit = v[cc] * LOGIT_SCALE;
                    if (hasPos && c == (r ^ 4096)) { g_pos[r] = logit; g_pos[c] = logit; }
                    float ev = __expf(logit - 10.0f);
                    if (isDiag && r == c) ev = 0.f;
                    rs[mi][hh] += ev;
                    cs[ni][cc] += ev;
                }
            }

    // rows: reduce over tIdx (xor 1,2)
#pragma unroll
    for (int off = 1; off <= 2; off <<= 1)
#pragma unroll
        for (int mi = 0; mi < 4; mi++)
#pragma unroll
            for (int h = 0; h < 2; h++)
                rs[mi][h] += __shfl_xor_sync(0xffffffffu, rs[mi][h], off);
    {
        const int mi = tIdx;
        const int r = r0 + warp_m * 64 + mi * 16 + groupID;
        atomicAdd(&g_rowsum[r],     rs[mi][0]);
        atomicAdd(&g_rowsum[r + 8], rs[mi][1]);
    }

    // cols: reduce over groupID (xor 4,8,16), off-diag only
    if (!isDiag) {
#pragma unroll
        for (int off = 4; off <= 16; off <<= 1)
#pragma unroll
            for (int ni = 0; ni < 8; ni++)
#pragma unroll
                for (int h = 0; h < 2; h++)
                    cs[ni][h] += __shfl_xor_sync(0xffffffffu, cs[ni][h], off);
        const int ni = lane >> 2;
        const int c = c0 + warp_n * 64 + ni * 8 + (lane & 3) * 2;
        atomicAdd(&g_rowsum[c],     cs[ni][0]);
        atomicAdd(&g_rowsum[c + 1], cs[ni][1]);
    }
}

// ---------------------------------------------------------------------------
// Kernel 4: nll_i = -pos_i + 10 + log(rowsum_i); out = mean(nll)
// ---------------------------------------------------------------------------
__global__ __launch_bounds__(1024) void final_kernel(float* __restrict__ out) {
    __shared__ float red[1024];
    float s = 0.f;
    for (int i = threadIdx.x; i < NB; i += 1024)
        s += -g_pos[i] + 10.0f + logf(g_rowsum[i]);
    red[threadIdx.x] = s;
    __syncthreads();
    for (int off = 512; off > 0; off >>= 1) {
        if (threadIdx.x < off) red[threadIdx.x] += red[threadIdx.x + off];
        __syncthreads();
    }
    if (threadIdx.x == 0) out[0] = red[0] / (float)NB;
}

// ---------------------------------------------------------------------------
extern "C" void kernel_launch(void* const* d_in, const int* in_sizes, int n_in,
                              void* d_out, int out_size) {
    const float* x = (const float*)d_in[0];
    const float* w = (const float*)d_in[1];
    const float* b = (const float*)d_in[2];
    float* out = (float*)d_out;

    cudaFuncSetAttribute(proj_kernel, cudaFuncAttributeMaxDynamicSharedMemorySize, PROJ_SMEM);
    cudaFuncSetAttribute(sim_kernel,  cudaFuncAttributeMaxDynamicSharedMemorySize, SIM_SMEM);

    convert_kernel<<<XCVT_BLOCKS + WCVT_BLOCKS, 256>>>(x, w);
    dim3 g1(P_DIM / 128, M2 / 128);          // 512 blocks, single wave @ 4 CTAs/SM
    proj_kernel<<<g1, 128, PROJ_SMEM>>>(b);
    norm_kernel<<<NB, 256>>>();
    sim_kernel<<<TRI_BLOCKS, 128, SIM_SMEM>>>();
    final_kernel<<<1, 1024>>>(out);
}

// round 15
// speedup vs baseline: 1.0535x; 1.0535x over previous
#include <cuda_runtime.h>
#include <cuda_bf16.h>
#include <cuda_fp16.h>
#include <math.h>
#include <stdint.h>

#define NB       8192      // batch B
#define E_DIM    1024
#define P_DIM    512
#define D_DIM    1024      // 2P
#define M2       16384     // 2B rows in projection GEMM

// Scratch (no allocations allowed)
__device__ __half g_zb[(size_t)NB * D_DIM];             // 16 MB f16 proj output z
__device__ __half g_znh[(size_t)NB * D_DIM];            // 16 MB f16 normalized
__device__ __half g_xh[(size_t)NB * 2 * E_DIM];         // 32 MB f16 relu(x)
__device__ __half g_wh[(size_t)E_DIM * P_DIM];          // 1 MB f16 w
__device__ float g_rowsum[NB];
__device__ float g_pos[NB];

// ---------------------------------------------------------------------------
// PTX helpers (sm_80-era only)
// ---------------------------------------------------------------------------
__device__ __forceinline__ uint32_t smem_u32(const void* p) {
    uint32_t a;
    asm("{ .reg .u64 t; cvta.to.shared.u64 t, %1; cvt.u32.u64 %0, t; }" : "=r"(a) : "l"(p));
    return a;
}
__device__ __forceinline__ void cp_async16(uint32_t dst, const void* src) {
    asm volatile("cp.async.cg.shared.global [%0], [%1], 16;" :: "r"(dst), "l"(src));
}
#define CP_COMMIT() asm volatile("cp.async.commit_group;" ::: "memory")
#define CP_WAIT(N)  asm volatile("cp.async.wait_group %0;" :: "n"(N) : "memory")

__device__ __forceinline__ void ldsm_x4(uint32_t& r0, uint32_t& r1, uint32_t& r2,
                                        uint32_t& r3, uint32_t addr) {
    asm volatile("ldmatrix.sync.aligned.m8n8.x4.shared.b16 {%0,%1,%2,%3}, [%4];"
                 : "=r"(r0), "=r"(r1), "=r"(r2), "=r"(r3) : "r"(addr));
}
__device__ __forceinline__ void ldsm_x4_t(uint32_t& r0, uint32_t& r1, uint32_t& r2,
                                          uint32_t& r3, uint32_t addr) {
    asm volatile("ldmatrix.sync.aligned.m8n8.x4.trans.shared.b16 {%0,%1,%2,%3}, [%4];"
                 : "=r"(r0), "=r"(r1), "=r"(r2), "=r"(r3) : "r"(addr));
}
// f16 inputs, f16 accumulators (2 regs)
__device__ __forceinline__ void mma_f16(uint32_t* c, const uint32_t* a, const uint32_t* b) {
    asm volatile(
        "mma.sync.aligned.m16n8k16.row.col.f16.f16.f16.f16 "
        "{%0,%1}, {%2,%3,%4,%5}, {%6,%7}, {%0,%1};"
        : "+r"(c[0]), "+r"(c[1])
        : "r"(a[0]), "r"(a[1]), "r"(a[2]), "r"(a[3]), "r"(b[0]), "r"(b[1]));
}

// ---------------------------------------------------------------------------
// Kernel 0: convert relu(x)->f16 (g_xh) and w->f16 (g_wh)
// ---------------------------------------------------------------------------
#define XCVT_BLOCKS 16384
#define WCVT_BLOCKS 512
__global__ __launch_bounds__(256) void convert_kernel(const float* __restrict__ x,
                                                      const float* __restrict__ w) {
    const int tid = threadIdx.x;
    if (blockIdx.x < XCVT_BLOCKS) {
        const size_t i = ((size_t)blockIdx.x * 256 + tid);
        float4 v = *(const float4*)(x + i * 4);
        __half2 p0 = __floats2half2_rn(fmaxf(v.x, 0.f), fmaxf(v.y, 0.f));
        __half2 p1 = __floats2half2_rn(fmaxf(v.z, 0.f), fmaxf(v.w, 0.f));
        uint2 o; o.x = *(uint32_t*)&p0; o.y = *(uint32_t*)&p1;
        *(uint2*)(g_xh + i * 4) = o;
    } else {
        const size_t i = ((size_t)(blockIdx.x - XCVT_BLOCKS) * 256 + tid);
        float4 v = *(const float4*)(w + i * 4);
        __half2 p0 = __floats2half2_rn(v.x, v.y);
        __half2 p1 = __floats2half2_rn(v.z, v.w);
        uint2 o; o.x = *(uint32_t*)&p0; o.y = *(uint32_t*)&p1;
        *(uint2*)(g_wh + i * 4) = o;
    }
}

// ---------------------------------------------------------------------------
// Kernel 1: f16-acc HMMA projection (R13, unchanged), 4 CTAs/SM single wave.
// ---------------------------------------------------------------------------
#define AROW_BYTES  80
#define PA_BYTES    (128 * AROW_BYTES)       // 10240
#define BROW_BYTES  272                      // 128 f16 + 16B pad
#define PB_BYTES    (32 * BROW_BYTES)        // 8704
#define PSTAGE      (PA_BYTES + PB_BYTES)    // 18944
#define PSTAGES     3
#define PROJ_SMEM   (PSTAGES * PSTAGE)       // 56832
#define PCHUNKS     (E_DIM / 32)             // 32

extern __shared__ char dsmem[];

__device__ __forceinline__ void proj_prefetch(uint32_t stA, uint32_t stB,
                                              int m0, int n0, int kb, int tid) {
#pragma unroll
    for (int it = 0; it < 4; it++) {        // A: 128 rows x 4 segs
        const int j = tid + it * 128;
        const int row = j >> 2, seg = j & 3;
        const int r = m0 + row;
        const __half* src = g_xh + (size_t)(r & (NB - 1)) * 2048
                          + (size_t)(r >> 13) * 1024 + kb + (seg << 3);
        cp_async16(stA + row * AROW_BYTES + seg * 16, src);
    }
#pragma unroll
    for (int it = 0; it < 4; it++) {        // B: 32 k-rows x 16 segs
        const int j = tid + it * 128;
        const int row = j >> 4, seg = j & 15;
        const __half* src = g_wh + (size_t)(kb + row) * P_DIM + n0 + (seg << 3);
        cp_async16(stB + row * BROW_BYTES + seg * 16, src);
    }
}

__global__ __launch_bounds__(128, 4)
void proj_kernel(const float* __restrict__ bias) {
    const int tid = threadIdx.x;
    const int wid = tid >> 5;
    const int lane = tid & 31;
    const int warp_m = wid >> 1;
    const int warp_n = wid & 1;
    const int m0 = blockIdx.y * 128;
    const int n0 = blockIdx.x * 128;

    const uint32_t sbase = smem_u32(dsmem);
    uint32_t stA[PSTAGES], stB[PSTAGES];
#pragma unroll
    for (int s = 0; s < PSTAGES; s++) {
        stA[s] = sbase + s * PSTAGE;
        stB[s] = stA[s] + PA_BYTES;
    }

    const uint32_t aOff = (warp_m * 64 + (lane & 15)) * AROW_BYTES + (lane >> 4) * 16;
    const uint32_t bRow = (lane & 7) + ((lane >> 3) & 1) * 8;
    const uint32_t bCol = warp_n * 64 + (lane >> 4) * 8;

    uint32_t acc[4][8][2];
#pragma unroll
    for (int mi = 0; mi < 4; mi++)
#pragma unroll
        for (int ni = 0; ni < 8; ni++) { acc[mi][ni][0] = 0u; acc[mi][ni][1] = 0u; }

    proj_prefetch(stA[0], stB[0], m0, n0, 0, tid);  CP_COMMIT();
    proj_prefetch(stA[1], stB[1], m0, n0, 32, tid); CP_COMMIT();

    for (int kc = 0; kc < PCHUNKS; kc++) {
        CP_WAIT(1);
        __syncthreads();
        const int s = kc % PSTAGES;

#pragma unroll
        for (int ks = 0; ks < 2; ks++) {
            uint32_t aF[4][4], bF[4][4];
#pragma unroll
            for (int mi = 0; mi < 4; mi++)
                ldsm_x4(aF[mi][0], aF[mi][1], aF[mi][2], aF[mi][3],
                        stA[s] + aOff + mi * 16 * AROW_BYTES + ks * 32);
#pragma unroll
            for (int p = 0; p < 4; p++)
                ldsm_x4_t(bF[p][0], bF[p][1], bF[p][2], bF[p][3],
                          stB[s] + (ks * 16 + bRow) * BROW_BYTES + (bCol + p * 16) * 2);

            if (ks == 0) {
                if (kc + 2 < PCHUNKS) {
                    const int sn = (kc + 2) % PSTAGES;
                    proj_prefetch(stA[sn], stB[sn], m0, n0, (kc + 2) * 32, tid);
                }
                CP_COMMIT();
            }

#pragma unroll
            for (int mi = 0; mi < 4; mi++)
#pragma unroll
                for (int ni = 0; ni < 8; ni++)
                    mma_f16(acc[mi][ni], aF[mi], &bF[ni >> 1][(ni & 1) * 2]);
        }
    }

    const int groupID = lane >> 2, tIdx = lane & 3;
    const int cb = n0 + warp_n * 64 + tIdx * 2;
#pragma unroll
    for (int mi = 0; mi < 4; mi++)
#pragma unroll
        for (int hh = 0; hh < 2; hh++) {
            const int r = m0 + warp_m * 64 + mi * 16 + hh * 8 + groupID;
            const int ib = r & (NB - 1);
            const int half_sel = r >> 13;
            __half* outRow = g_zb + (size_t)ib * D_DIM + half_sel * P_DIM;
#pragma unroll
            for (int ni = 0; ni < 8; ni++) {
                const int c = cb + ni * 8;
                __half2 hv = *(__half2*)&acc[mi][ni][hh];
                __half2 v = __floats2half2_rn(
                    __half2float(hv.x) + __ldg(bias + c),
                    __half2float(hv.y) + __ldg(bias + c + 1));
                *(uint32_t*)(outRow + c) = *(uint32_t*)&v;
            }
        }
}

// ---------------------------------------------------------------------------
// Kernel 2: per-row L2 normalize (f16 in) -> f16 g_znh, zeroes g_rowsum
// ---------------------------------------------------------------------------
__global__ __launch_bounds__(256) void norm_kernel() {
    __shared__ float red[256];
    const __half* row = g_zb + (size_t)blockIdx.x * D_DIM;
    uint2 u = *(const uint2*)(row + threadIdx.x * 4);
    __half2 b0 = *(__half2*)&u.x;
    __half2 b1 = *(__half2*)&u.y;
    float v0 = __half2float(b0.x), v1 = __half2float(b0.y);
    float v2 = __half2float(b1.x), v3 = __half2float(b1.y);
    red[threadIdx.x] = v0 * v0 + v1 * v1 + v2 * v2 + v3 * v3;
    __syncthreads();
    for (int off = 128; off > 0; off >>= 1) {
        if (threadIdx.x < off) red[threadIdx.x] += red[threadIdx.x + off];
        __syncthreads();
    }
    const float inv = 1.0f / fmaxf(sqrtf(red[0]), 1e-8f);
    __half2 p0 = __floats2half2_rn(v0 * inv, v1 * inv);
    __half2 p1 = __floats2half2_rn(v2 * inv, v3 * inv);
    uint2 o; o.x = *(uint32_t*)&p0; o.y = *(uint32_t*)&p1;
    *(uint2*)(g_znh + (size_t)blockIdx.x * D_DIM + threadIdx.x * 4) = o;
    if (threadIdx.x == 0) g_rowsum[blockIdx.x] = 0.f;
}

// ---------------------------------------------------------------------------
// Kernel 3: f16-acc HMMA sim GEMM (upper triangle), block 128x128, 4 warps
// (64x64), BK=32, 2 stages, WAIT(1), serial per-ks frags -> 4 CTAs/SM.
// ---------------------------------------------------------------------------
#define ROW_BYTES   80
#define TILE_BYTES  (128 * ROW_BYTES)
#define STAGE_BYTES (2 * TILE_BYTES)         // 20480
#define SSTAGES     2
#define SIM_SMEM    (SSTAGES * STAGE_BYTES)  // 40960
#define SCHUNKS     (D_DIM / 32)             // 32
#define TRI_BLOCKS  2080

__device__ __forceinline__ void sim_prefetch(uint32_t stageA, uint32_t stageB,
                                             int r0, int c0, int kb, int tid) {
#pragma unroll
    for (int it = 0; it < 4; it++) {
        const int i = tid + it * 128;
        const int row = i >> 2, seg = i & 3;
        const uint32_t d = row * ROW_BYTES + seg * 16;
        cp_async16(stageA + d, g_znh + (((size_t)(r0 + row)) << 10) + kb + (seg << 3));
        cp_async16(stageB + d, g_znh + (((size_t)(c0 + row)) << 10) + kb + (seg << 3));
    }
}

__global__ __launch_bounds__(128, 4)
void sim_kernel() {
    // map t -> (by, bx) upper triangle, bx >= by
    const int t = blockIdx.x;
    int by = (int)((129.0f - sqrtf(129.0f * 129.0f - 8.0f * (float)t)) * 0.5f);
    if (by > 63) by = 63;
    if (by < 0) by = 0;
    while (by * 64 - (by * (by - 1)) / 2 > t) by--;
    while ((by + 1) * 64 - ((by + 1) * by) / 2 <= t) by++;
    const int bx = by + (t - (by * 64 - (by * (by - 1)) / 2));

    const int tid = threadIdx.x;
    const int wid = tid >> 5;
    const int lane = tid & 31;
    const int warp_m = wid >> 1;             // 0..1
    const int warp_n = wid & 1;              // 0..1
    const int r0 = by * 128;
    const int c0 = bx * 128;

    const uint32_t sbase = smem_u32(dsmem);
    uint32_t stA[SSTAGES], stB[SSTAGES];
#pragma unroll
    for (int s = 0; s < SSTAGES; s++) {
        stA[s] = sbase + s * STAGE_BYTES;
        stB[s] = stA[s] + TILE_BYTES;
    }

    const uint32_t aOff = (warp_m * 64 + (lane & 15)) * ROW_BYTES + (lane >> 4) * 16;
    const uint32_t bOff = (warp_n * 64 + ((lane >> 4) & 1) * 8 + (lane & 7)) * ROW_BYTES
                        + ((lane >> 3) & 1) * 16;

    uint32_t acc[4][8][2];                   // f16x2 accumulators
#pragma unroll
    for (int mi = 0; mi < 4; mi++)
#pragma unroll
        for (int ni = 0; ni < 8; ni++) { acc[mi][ni][0] = 0u; acc[mi][ni][1] = 0u; }

    sim_prefetch(stA[0], stB[0], r0, c0, 0, tid);  CP_COMMIT();
    sim_prefetch(stA[1], stB[1], r0, c0, 32, tid); CP_COMMIT();

    for (int kc = 0; kc < SCHUNKS; kc++) {
        CP_WAIT(1);
        __syncthreads();
        const int s = kc & 1;

        // ks0: load frags + mma
        {
            uint32_t aF[4][4], bF[4][4];
#pragma unroll
            for (int mi = 0; mi < 4; mi++)
                ldsm_x4(aF[mi][0], aF[mi][1], aF[mi][2], aF[mi][3],
                        stA[s] + aOff + mi * 16 * ROW_BYTES);
#pragma unroll
            for (int p = 0; p < 4; p++)
                ldsm_x4(bF[p][0], bF[p][1], bF[p][2], bF[p][3],
                        stB[s] + bOff + p * 16 * ROW_BYTES);
#pragma unroll
            for (int mi = 0; mi < 4; mi++)
#pragma unroll
                for (int ni = 0; ni < 8; ni++)
                    mma_f16(acc[mi][ni], aF[mi], &bF[ni >> 1][(ni & 1) * 2]);
        }
        // ks1: load frags, then sync + prefetch (stage fully read), then mma
        {
            uint32_t aF[4][4], bF[4][4];
#pragma unroll
            for (int mi = 0; mi < 4; mi++)
                ldsm_x4(aF[mi][0], aF[mi][1], aF[mi][2], aF[mi][3],
                        stA[s] + aOff + mi * 16 * ROW_BYTES + 32);
#pragma unroll
            for (int p = 0; p < 4; p++)
                ldsm_x4(bF[p][0], bF[p][1], bF[p][2], bF[p][3],
                        stB[s] + bOff + p * 16 * ROW_BYTES + 32);

            __syncthreads();                 // all warps done reading stage s
            if (kc + 2 < SCHUNKS)
                sim_prefetch(stA[s], stB[s], r0, c0, (kc + 2) * 32, tid);
            CP_COMMIT();

#pragma unroll
            for (int mi = 0; mi < 4; mi++)
#pragma unroll
                for (int ni = 0; ni < 8; ni++)
                    mma_f16(acc[mi][ni], aF[mi], &bF[ni >> 1][(ni & 1) * 2]);
        }
    }

    // ---------------- fused epilogue ----------------
    const bool isDiag = (bx == by);
    const bool hasPos = (bx == (by ^ 32));
    const int groupID = lane >> 2, tIdx = lane & 3;
    const int rbase = r0 + warp_m * 64 + groupID;
    const int cbase = c0 + warp_n * 64 + tIdx * 2;

    float rs[4][2];                          // [mi][rowhalf]
    float cs[8][2];                          // [ni][colpair]
#pragma unroll
    for (int i = 0; i < 4; i++) { rs[i][0] = rs[i][1] = 0.f; }
#pragma unroll
    for (int i = 0; i < 8; i++) { cs[i][0] = cs[i][1] = 0.f; }

#pragma unroll
    for (int mi = 0; mi < 4; mi++)
#pragma unroll
        for (int ni = 0; ni < 8; ni++)
#pragma unroll
            for (int hh = 0; hh < 2; hh++) {
                const int r = rbase + mi * 16 + hh * 8;
                __half2 hv = *(__half2*)&acc[mi][ni][hh];
                float v[2] = {__half2float(hv.x), __half2float(hv.y)};
#pragma unroll
                for (int cc = 0; cc < 2; cc++) {
                    const int c = cbase + ni * 8 + cc;
                    const float logit = v[cc] * 10.0f;
                    if (hasPos && c == (r ^ 4096)) { g_pos[r] = logit; g_pos[c] = logit; }
                    float ev = __expf(logit - 10.0f);
                    if (isDiag && r == c) ev = 0.f;
                    rs[mi][hh] += ev;
                    cs[ni][cc] += ev;
                }
            }

    // rows: reduce over tIdx (xor 1,2)
#pragma unroll
    for (int off = 1; off <= 2; off <<= 1)
#pragma unroll
        for (int mi = 0; mi < 4; mi++)
#pragma unroll
            for (int h = 0; h < 2; h++)
                rs[mi][h] += __shfl_xor_sync(0xffffffffu, rs[mi][h], off);
    {
        const int mi = tIdx;
        const int r = r0 + warp_m * 64 + mi * 16 + groupID;
        atomicAdd(&g_rowsum[r],     rs[mi][0]);
        atomicAdd(&g_rowsum[r + 8], rs[mi][1]);
    }

    // cols: reduce over groupID (xor 4,8,16), off-diag only
    if (!isDiag) {
#pragma unroll
        for (int off = 4; off <= 16; off <<= 1)
#pragma unroll
            for (int ni = 0; ni < 8; ni++)
#pragma unroll
                for (int h = 0; h < 2; h++)
                    cs[ni][h] += __shfl_xor_sync(0xffffffffu, cs[ni][h], off);
        const int ni = lane >> 2;
        const int c = c0 + warp_n * 64 + ni * 8 + (lane & 3) * 2;
        atomicAdd(&g_rowsum[c],     cs[ni][0]);
        atomicAdd(&g_rowsum[c + 1], cs[ni][1]);
    }
}

// ---------------------------------------------------------------------------
// Kernel 4: nll_i = -pos_i + 10 + log(rowsum_i); out = mean(nll)
// ---------------------------------------------------------------------------
__global__ __launch_bounds__(1024) void final_kernel(float* __restrict__ out) {
    __shared__ float red[1024];
    float s = 0.f;
    for (int i = threadIdx.x; i < NB; i += 1024)
        s += -g_pos[i] + 10.0f + logf(g_rowsum[i]);
    red[threadIdx.x] = s;
    __syncthreads();
    for (int off = 512; off > 0; off >>= 1) {
        if (threadIdx.x < off) red[threadIdx.x] += red[threadIdx.x + off];
        __syncthreads();
    }
    if (threadIdx.x == 0) out[0] = red[0] / (float)NB;
}

// ---------------------------------------------------------------------------
extern "C" void kernel_launch(void* const* d_in, const int* in_sizes, int n_in,
                              void* d_out, int out_size) {
    const float* x = (const float*)d_in[0];
    const float* w = (const float*)d_in[1];
    const float* b = (const float*)d_in[2];
    float* out = (float*)d_out;

    cudaFuncSetAttribute(proj_kernel, cudaFuncAttributeMaxDynamicSharedMemorySize, PROJ_SMEM);
    cudaFuncSetAttribute(sim_kernel,  cudaFuncAttributeMaxDynamicSharedMemorySize, SIM_SMEM);

    convert_kernel<<<XCVT_BLOCKS + WCVT_BLOCKS, 256>>>(x, w);
    dim3 g1(P_DIM / 128, M2 / 128);          // 512 blocks, single wave @ 4 CTAs/SM
    proj_kernel<<<g1, 128, PROJ_SMEM>>>(b);
    norm_kernel<<<NB, 256>>>();
    sim_kernel<<<TRI_BLOCKS, 128, SIM_SMEM>>>();
    final_kernel<<<1, 1024>>>(out);
}

// round 16
// speedup vs baseline: 1.1056x; 1.0495x over previous
#include <cuda_runtime.h>
#include <cuda_bf16.h>
#include <cuda_fp16.h>
#include <math.h>
#include <stdint.h>

#define NB       8192      // batch B
#define E_DIM    1024
#define P_DIM    512
#define D_DIM    1024      // 2P
#define M2       16384     // 2B rows in projection GEMM

// Scratch (no allocations allowed)
__device__ __half g_zb[(size_t)NB * D_DIM];             // 16 MB f16 proj output z
__device__ __half g_znh[(size_t)NB * D_DIM];            // 16 MB f16 normalized
__device__ __half g_xh[(size_t)NB * 2 * E_DIM];         // 32 MB f16 relu(x)
__device__ __half g_wh[(size_t)E_DIM * P_DIM];          // 1 MB f16 w
__device__ float g_rowsum[NB];
__device__ float g_pos[NB];

// ---------------------------------------------------------------------------
// PTX helpers (sm_80-era only)
// ---------------------------------------------------------------------------
__device__ __forceinline__ uint32_t smem_u32(const void* p) {
    uint32_t a;
    asm("{ .reg .u64 t; cvta.to.shared.u64 t, %1; cvt.u32.u64 %0, t; }" : "=r"(a) : "l"(p));
    return a;
}
__device__ __forceinline__ void cp_async16(uint32_t dst, const void* src) {
    asm volatile("cp.async.cg.shared.global [%0], [%1], 16;" :: "r"(dst), "l"(src));
}
#define CP_COMMIT() asm volatile("cp.async.commit_group;" ::: "memory")
#define CP_WAIT(N)  asm volatile("cp.async.wait_group %0;" :: "n"(N) : "memory")

__device__ __forceinline__ void ldsm_x4(uint32_t& r0, uint32_t& r1, uint32_t& r2,
                                        uint32_t& r3, uint32_t addr) {
    asm volatile("ldmatrix.sync.aligned.m8n8.x4.shared.b16 {%0,%1,%2,%3}, [%4];"
                 : "=r"(r0), "=r"(r1), "=r"(r2), "=r"(r3) : "r"(addr));
}
__device__ __forceinline__ void ldsm_x4_t(uint32_t& r0, uint32_t& r1, uint32_t& r2,
                                          uint32_t& r3, uint32_t addr) {
    asm volatile("ldmatrix.sync.aligned.m8n8.x4.trans.shared.b16 {%0,%1,%2,%3}, [%4];"
                 : "=r"(r0), "=r"(r1), "=r"(r2), "=r"(r3) : "r"(addr));
}
// f16 inputs, f16 accumulators (2 regs)
__device__ __forceinline__ void mma_f16(uint32_t* c, const uint32_t* a, const uint32_t* b) {
    asm volatile(
        "mma.sync.aligned.m16n8k16.row.col.f16.f16.f16.f16 "
        "{%0,%1}, {%2,%3,%4,%5}, {%6,%7}, {%0,%1};"
        : "+r"(c[0]), "+r"(c[1])
        : "r"(a[0]), "r"(a[1]), "r"(a[2]), "r"(a[3]), "r"(b[0]), "r"(b[1]));
}

// ---------------------------------------------------------------------------
// Kernel 0: convert relu(x)->f16 (g_xh) and w->f16 (g_wh), 8 floats/thread
// ---------------------------------------------------------------------------
#define XCVT_BLOCKS 8192             // 8192*2048 elems / (256 thr * 8 elems)
#define WCVT_BLOCKS 256              // 1024*512 / (256 * 8)
__global__ __launch_bounds__(256) void convert_kernel(const float* __restrict__ x,
                                                      const float* __restrict__ w) {
    const int tid = threadIdx.x;
    if (blockIdx.x < XCVT_BLOCKS) {
        const size_t i = ((size_t)blockIdx.x * 256 + tid);
#pragma unroll
        for (int h = 0; h < 2; h++) {
            const size_t e = i * 8 + h * 4;
            float4 v = *(const float4*)(x + e);
            __half2 p0 = __floats2half2_rn(fmaxf(v.x, 0.f), fmaxf(v.y, 0.f));
            __half2 p1 = __floats2half2_rn(fmaxf(v.z, 0.f), fmaxf(v.w, 0.f));
            uint2 o; o.x = *(uint32_t*)&p0; o.y = *(uint32_t*)&p1;
            *(uint2*)(g_xh + e) = o;
        }
    } else {
        const size_t i = ((size_t)(blockIdx.x - XCVT_BLOCKS) * 256 + tid);
#pragma unroll
        for (int h = 0; h < 2; h++) {
            const size_t e = i * 8 + h * 4;
            float4 v = *(const float4*)(w + e);
            __half2 p0 = __floats2half2_rn(v.x, v.y);
            __half2 p1 = __floats2half2_rn(v.z, v.w);
            uint2 o; o.x = *(uint32_t*)&p0; o.y = *(uint32_t*)&p1;
            *(uint2*)(g_wh + e) = o;
        }
    }
}

// ---------------------------------------------------------------------------
// Kernel 1: f16-acc HMMA projection (R13, unchanged), 4 CTAs/SM single wave.
// ---------------------------------------------------------------------------
#define AROW_BYTES  80
#define PA_BYTES    (128 * AROW_BYTES)       // 10240
#define BROW_BYTES  272                      // 128 f16 + 16B pad
#define PB_BYTES    (32 * BROW_BYTES)        // 8704
#define PSTAGE      (PA_BYTES + PB_BYTES)    // 18944
#define PSTAGES     3
#define PROJ_SMEM   (PSTAGES * PSTAGE)       // 56832
#define PCHUNKS     (E_DIM / 32)             // 32

extern __shared__ char dsmem[];

__device__ __forceinline__ void proj_prefetch(uint32_t stA, uint32_t stB,
                                              int m0, int n0, int kb, int tid) {
#pragma unroll
    for (int it = 0; it < 4; it++) {        // A: 128 rows x 4 segs
        const int j = tid + it * 128;
        const int row = j >> 2, seg = j & 3;
        const int r = m0 + row;
        const __half* src = g_xh + (size_t)(r & (NB - 1)) * 2048
                          + (size_t)(r >> 13) * 1024 + kb + (seg << 3);
        cp_async16(stA + row * AROW_BYTES + seg * 16, src);
    }
#pragma unroll
    for (int it = 0; it < 4; it++) {        // B: 32 k-rows x 16 segs
        const int j = tid + it * 128;
        const int row = j >> 4, seg = j & 15;
        const __half* src = g_wh + (size_t)(kb + row) * P_DIM + n0 + (seg << 3);
        cp_async16(stB + row * BROW_BYTES + seg * 16, src);
    }
}

__global__ __launch_bounds__(128, 4)
void proj_kernel(const float* __restrict__ bias) {
    const int tid = threadIdx.x;
    const int wid = tid >> 5;
    const int lane = tid & 31;
    const int warp_m = wid >> 1;
    const int warp_n = wid & 1;
    const int m0 = blockIdx.y * 128;
    const int n0 = blockIdx.x * 128;

    const uint32_t sbase = smem_u32(dsmem);
    uint32_t stA[PSTAGES], stB[PSTAGES];
#pragma unroll
    for (int s = 0; s < PSTAGES; s++) {
        stA[s] = sbase + s * PSTAGE;
        stB[s] = stA[s] + PA_BYTES;
    }

    const uint32_t aOff = (warp_m * 64 + (lane & 15)) * AROW_BYTES + (lane >> 4) * 16;
    const uint32_t bRow = (lane & 7) + ((lane >> 3) & 1) * 8;
    const uint32_t bCol = warp_n * 64 + (lane >> 4) * 8;

    uint32_t acc[4][8][2];
#pragma unroll
    for (int mi = 0; mi < 4; mi++)
#pragma unroll
        for (int ni = 0; ni < 8; ni++) { acc[mi][ni][0] = 0u; acc[mi][ni][1] = 0u; }

    proj_prefetch(stA[0], stB[0], m0, n0, 0, tid);  CP_COMMIT();
    proj_prefetch(stA[1], stB[1], m0, n0, 32, tid); CP_COMMIT();

    for (int kc = 0; kc < PCHUNKS; kc++) {
        CP_WAIT(1);
        __syncthreads();
        const int s = kc % PSTAGES;

#pragma unroll
        for (int ks = 0; ks < 2; ks++) {
            uint32_t aF[4][4], bF[4][4];
#pragma unroll
            for (int mi = 0; mi < 4; mi++)
                ldsm_x4(aF[mi][0], aF[mi][1], aF[mi][2], aF[mi][3],
                        stA[s] + aOff + mi * 16 * AROW_BYTES + ks * 32);
#pragma unroll
            for (int p = 0; p < 4; p++)
                ldsm_x4_t(bF[p][0], bF[p][1], bF[p][2], bF[p][3],
                          stB[s] + (ks * 16 + bRow) * BROW_BYTES + (bCol + p * 16) * 2);

            if (ks == 0) {
                if (kc + 2 < PCHUNKS) {
                    const int sn = (kc + 2) % PSTAGES;
                    proj_prefetch(stA[sn], stB[sn], m0, n0, (kc + 2) * 32, tid);
                }
                CP_COMMIT();
            }

#pragma unroll
            for (int mi = 0; mi < 4; mi++)
#pragma unroll
                for (int ni = 0; ni < 8; ni++)
                    mma_f16(acc[mi][ni], aF[mi], &bF[ni >> 1][(ni & 1) * 2]);
        }
    }

    const int groupID = lane >> 2, tIdx = lane & 3;
    const int cb = n0 + warp_n * 64 + tIdx * 2;
#pragma unroll
    for (int mi = 0; mi < 4; mi++)
#pragma unroll
        for (int hh = 0; hh < 2; hh++) {
            const int r = m0 + warp_m * 64 + mi * 16 + hh * 8 + groupID;
            const int ib = r & (NB - 1);
            const int half_sel = r >> 13;
            __half* outRow = g_zb + (size_t)ib * D_DIM + half_sel * P_DIM;
#pragma unroll
            for (int ni = 0; ni < 8; ni++) {
                const int c = cb + ni * 8;
                __half2 hv = *(__half2*)&acc[mi][ni][hh];
                __half2 v = __floats2half2_rn(
                    __half2float(hv.x) + __ldg(bias + c),
                    __half2float(hv.y) + __ldg(bias + c + 1));
                *(uint32_t*)(outRow + c) = *(uint32_t*)&v;
            }
        }
}

// ---------------------------------------------------------------------------
// Kernel 2: per-row L2 normalize (f16 in) -> f16 g_znh, zeroes g_rowsum
// ---------------------------------------------------------------------------
__global__ __launch_bounds__(256) void norm_kernel() {
    __shared__ float red[256];
    const __half* row = g_zb + (size_t)blockIdx.x * D_DIM;
    uint2 u = *(const uint2*)(row + threadIdx.x * 4);
    __half2 b0 = *(__half2*)&u.x;
    __half2 b1 = *(__half2*)&u.y;
    float v0 = __half2float(b0.x), v1 = __half2float(b0.y);
    float v2 = __half2float(b1.x), v3 = __half2float(b1.y);
    red[threadIdx.x] = v0 * v0 + v1 * v1 + v2 * v2 + v3 * v3;
    __syncthreads();
    for (int off = 128; off > 0; off >>= 1) {
        if (threadIdx.x < off) red[threadIdx.x] += red[threadIdx.x + off];
        __syncthreads();
    }
    const float inv = 1.0f / fmaxf(sqrtf(red[0]), 1e-8f);
    __half2 p0 = __floats2half2_rn(v0 * inv, v1 * inv);
    __half2 p1 = __floats2half2_rn(v2 * inv, v3 * inv);
    uint2 o; o.x = *(uint32_t*)&p0; o.y = *(uint32_t*)&p1;
    *(uint2*)(g_znh + (size_t)blockIdx.x * D_DIM + threadIdx.x * 4) = o;
    if (threadIdx.x == 0) g_rowsum[blockIdx.x] = 0.f;
}

// ---------------------------------------------------------------------------
// Kernel 3: f16-acc HMMA sim GEMM (upper triangle), block 128x128, 4 warps
// (64x64), BK=32, 2 stages, WAIT(1), serial per-ks frags, 4 CTAs/SM (R15).
// ---------------------------------------------------------------------------
#define ROW_BYTES   80
#define TILE_BYTES  (128 * ROW_BYTES)
#define STAGE_BYTES (2 * TILE_BYTES)         // 20480
#define SSTAGES     2
#define SIM_SMEM    (SSTAGES * STAGE_BYTES)  // 40960
#define SCHUNKS     (D_DIM / 32)             // 32
#define TRI_BLOCKS  2080

__device__ __forceinline__ void sim_prefetch(uint32_t stageA, uint32_t stageB,
                                             int r0, int c0, int kb, int tid) {
#pragma unroll
    for (int it = 0; it < 4; it++) {
        const int i = tid + it * 128;
        const int row = i >> 2, seg = i & 3;
        const uint32_t d = row * ROW_BYTES + seg * 16;
        cp_async16(stageA + d, g_znh + (((size_t)(r0 + row)) << 10) + kb + (seg << 3));
        cp_async16(stageB + d, g_znh + (((size_t)(c0 + row)) << 10) + kb + (seg << 3));
    }
}

__global__ __launch_bounds__(128, 4)
void sim_kernel() {
    // map t -> (by, bx) upper triangle, bx >= by
    const int t = blockIdx.x;
    int by = (int)((129.0f - sqrtf(129.0f * 129.0f - 8.0f * (float)t)) * 0.5f);
    if (by > 63) by = 63;
    if (by < 0) by = 0;
    while (by * 64 - (by * (by - 1)) / 2 > t) by--;
    while ((by + 1) * 64 - ((by + 1) * by) / 2 <= t) by++;
    const int bx = by + (t - (by * 64 - (by * (by - 1)) / 2));

    const int tid = threadIdx.x;
    const int wid = tid >> 5;
    const int lane = tid & 31;
    const int warp_m = wid >> 1;             // 0..1
    const int warp_n = wid & 1;              // 0..1
    const int r0 = by * 128;
    const int c0 = bx * 128;

    const uint32_t sbase = smem_u32(dsmem);
    uint32_t stA[SSTAGES], stB[SSTAGES];
#pragma unroll
    for (int s = 0; s < SSTAGES; s++) {
        stA[s] = sbase + s * STAGE_BYTES;
        stB[s] = stA[s] + TILE_BYTES;
    }

    const uint32_t aOff = (warp_m * 64 + (lane & 15)) * ROW_BYTES + (lane >> 4) * 16;
    const uint32_t bOff = (warp_n * 64 + ((lane >> 4) & 1) * 8 + (lane & 7)) * ROW_BYTES
                        + ((lane >> 3) & 1) * 16;

    uint32_t acc[4][8][2];                   // f16x2 accumulators
#pragma unroll
    for (int mi = 0; mi < 4; mi++)
#pragma unroll
        for (int ni = 0; ni < 8; ni++) { acc[mi][ni][0] = 0u; acc[mi][ni][1] = 0u; }

    sim_prefetch(stA[0], stB[0], r0, c0, 0, tid);  CP_COMMIT();
    sim_prefetch(stA[1], stB[1], r0, c0, 32, tid); CP_COMMIT();

    for (int kc = 0; kc < SCHUNKS; kc++) {
        CP_WAIT(1);
        __syncthreads();
        const int s = kc & 1;

        // ks0: load frags + mma
        {
            uint32_t aF[4][4], bF[4][4];
#pragma unroll
            for (int mi = 0; mi < 4; mi++)
                ldsm_x4(aF[mi][0], aF[mi][1], aF[mi][2], aF[mi][3],
                        stA[s] + aOff + mi * 16 * ROW_BYTES);
#pragma unroll
            for (int p = 0; p < 4; p++)
                ldsm_x4(bF[p][0], bF[p][1], bF[p][2], bF[p][3],
                        stB[s] + bOff + p * 16 * ROW_BYTES);
#pragma unroll
            for (int mi = 0; mi < 4; mi++)
#pragma unroll
                for (int ni = 0; ni < 8; ni++)
                    mma_f16(acc[mi][ni], aF[mi], &bF[ni >> 1][(ni & 1) * 2]);
        }
        // ks1: load frags, then sync + prefetch (stage fully read), then mma
        {
            uint32_t aF[4][4], bF[4][4];
#pragma unroll
            for (int mi = 0; mi < 4; mi++)
                ldsm_x4(aF[mi][0], aF[mi][1], aF[mi][2], aF[mi][3],
                        stA[s] + aOff + mi * 16 * ROW_BYTES + 32);
#pragma unroll
            for (int p = 0; p < 4; p++)
                ldsm_x4(bF[p][0], bF[p][1], bF[p][2], bF[p][3],
                        stB[s] + bOff + p * 16 * ROW_BYTES + 32);

            __syncthreads();                 // all warps done reading stage s
            if (kc + 2 < SCHUNKS)
                sim_prefetch(stA[s], stB[s], r0, c0, (kc + 2) * 32, tid);
            CP_COMMIT();

#pragma unroll
            for (int mi = 0; mi < 4; mi++)
#pragma unroll
                for (int ni = 0; ni < 8; ni++)
                    mma_f16(acc[mi][ni], aF[mi], &bF[ni >> 1][(ni & 1) * 2]);
        }
    }

    // ---------------- fused epilogue ----------------
    const bool isDiag = (bx == by);
    const bool hasPos = (bx == (by ^ 32));
    const int groupID = lane >> 2, tIdx = lane & 3;
    const int rbase = r0 + warp_m * 64 + groupID;
    const int cbase = c0 + warp_n * 64 + tIdx * 2;

    float rs[4][2];                          // [mi][rowhalf]
    float cs[8][2];                          // [ni][colpair]
#pragma unroll
    for (int i = 0; i < 4; i++) { rs[i][0] = rs[i][1] = 0.f; }
#pragma unroll
    for (int i = 0; i < 8; i++) { cs[i][0] = cs[i][1] = 0.f; }

#pragma unroll
    for (int mi = 0; mi < 4; mi++)
#pragma unroll
        for (int ni = 0; ni < 8; ni++)
#pragma unroll
            for (int hh = 0; hh < 2; hh++) {
                const int r = rbase + mi * 16 + hh * 8;
                __half2 hv = *(__half2*)&acc[mi][ni][hh];
                float v[2] = {__half2float(hv.x), __half2float(hv.y)};
#pragma unroll
                for (int cc = 0; cc < 2; cc++) {
                    const int c = cbase + ni * 8 + cc;
                    const float logit = v[cc] * 10.0f;
                    if (hasPos && c == (r ^ 4096)) { g_pos[r] = logit; g_pos[c] = logit; }
                    float ev = __expf(logit - 10.0f);
                    if (isDiag && r == c) ev = 0.f;
                    rs[mi][hh] += ev;
                    cs[ni][cc] += ev;
                }
            }

    // rows: reduce over tIdx (xor 1,2)
#pragma unroll
    for (int off = 1; off <= 2; off <<= 1)
#pragma unroll
        for (int mi = 0; mi < 4; mi++)
#pragma unroll
            for (int h = 0; h < 2; h++)
                rs[mi][h] += __shfl_xor_sync(0xffffffffu, rs[mi][h], off);
    {
        const int mi = tIdx;
        const int r = r0 + warp_m * 64 + mi * 16 + groupID;
        atomicAdd(&g_rowsum[r],     rs[mi][0]);
        atomicAdd(&g_rowsum[r + 8], rs[mi][1]);
    }

    // cols: reduce over groupID (xor 4,8,16), off-diag only
    if (!isDiag) {
#pragma unroll
        for (int off = 4; off <= 16; off <<= 1)
#pragma unroll
            for (int ni = 0; ni < 8; ni++)
#pragma unroll
                for (int h = 0; h < 2; h++)
                    cs[ni][h] += __shfl_xor_sync(0xffffffffu, cs[ni][h], off);
        const int ni = lane >> 2;
        const int c = c0 + warp_n * 64 + ni * 8 + (lane & 3) * 2;
        atomicAdd(&g_rowsum[c],     cs[ni][0]);
        atomicAdd(&g_rowsum[c + 1], cs[ni][1]);
    }
}

// ---------------------------------------------------------------------------
// Kernel 4: nll_i = -pos_i + 10 + log(rowsum_i); out = mean(nll)
// ---------------------------------------------------------------------------
__global__ __launch_bounds__(1024) void final_kernel(float* __restrict__ out) {
    __shared__ float red[1024];
    float s = 0.f;
    for (int i = threadIdx.x; i < NB; i += 1024)
        s += -g_pos[i] + 10.0f + logf(g_rowsum[i]);
    red[threadIdx.x] = s;
    __syncthreads();
    for (int off = 512; off > 0; off >>= 1) {
        if (threadIdx.x < off) red[threadIdx.x] += red[threadIdx.x + off];
        __syncthreads();
    }
    if (threadIdx.x == 0) out[0] = red[0] / (float)NB;
}

// ---------------------------------------------------------------------------
extern "C" void kernel_launch(void* const* d_in, const int* in_sizes, int n_in,
                              void* d_out, int out_size) {
    const float* x = (const float*)d_in[0];
    const float* w = (const float*)d_in[1];
    const float* b = (const float*)d_in[2];
    float* out = (float*)d_out;

    cudaFuncSetAttribute(proj_kernel, cudaFuncAttributeMaxDynamicSharedMemorySize, PROJ_SMEM);
    cudaFuncSetAttribute(sim_kernel,  cudaFuncAttributeMaxDynamicSharedMemorySize, SIM_SMEM);

    convert_kernel<<<XCVT_BLOCKS + WCVT_BLOCKS, 256>>>(x, w);
    dim3 g1(P_DIM / 128, M2 / 128);          // 512 blocks, single wave @ 4 CTAs/SM
    proj_kernel<<<g1, 128, PROJ_SMEM>>>(b);
    norm_kernel<<<NB, 256>>>();
    sim_kernel<<<TRI_BLOCKS, 128, SIM_SMEM>>>();
    final_kernel<<<1, 1024>>>(out);
}